// round 5
// baseline (speedup 1.0000x reference)
#include <cuda_runtime.h>

// Geometry (fixed: importanceMap [32, 1024, 1024] fp32)
#define NBATCH            32
#define ELEM_PER_BATCH    (1 << 20)
#define V4_PER_BATCH      (1 << 18)                  // float4 per batch
#define NBLK              512
#define THREADS           256
#define TASKS             4                          // batch-rounds per block
#define BLOCKS_PER_BATCH  64
#define BATCH_PER_ROUND   (NBLK / BLOCKS_PER_BATCH)  // 8
#define V4_PER_STRIPE     (V4_PER_BATCH / BLOCKS_PER_BATCH) // 4096 (64 KB)
#define ITERS             (V4_PER_STRIPE / THREADS)  // 16

// Deterministic scratch (no allocations). Partials: {sum s, sum s', sum s''}.
__device__ float4       g_partial[NBATCH][BLOCKS_PER_BATCH];
__device__ unsigned int g_bar[NBATCH];   // monotonic ticket counter per batch

__device__ __forceinline__ float rcp_fast(float x) {
    float r; asm("rcp.approx.f32 %0, %1;" : "=f"(r) : "f"(x)); return r;
}
__device__ __forceinline__ float tanh_fast(float x) {
    float r; asm("tanh.approx.f32 %0, %1;" : "=f"(r) : "f"(x)); return r;
}

// Deterministic per-batch solve from 64 block partials (fixed order ->
// bitwise-identical c in every block of the batch). Runs on warp 0.
__device__ __forceinline__ float solve_c(int batch, int lane)
{
    float4 pa = __ldcg(&g_partial[batch][lane]);
    float4 pb = __ldcg(&g_partial[batch][lane + 32]);
    float s0 = pa.x + pb.x, s1 = pa.y + pb.y, s2 = pa.z + pb.z;
    #pragma unroll
    for (int off = 16; off; off >>= 1) {
        s0 += __shfl_xor_sync(0xFFFFFFFFu, s0, off);
        s1 += __shfl_xor_sync(0xFFFFFFFFu, s1, off);
        s2 += __shfl_xor_sync(0xFFFFFFFFu, s2, off);
    }
    s0 = __shfl_sync(0xFFFFFFFFu, s0, 0);
    s1 = __shfl_sync(0xFFFFFFFFu, s1, 0);
    s2 = __shfl_sync(0xFFFFFFFFu, s2, 0);

    const double invN = 1.0 / (double)ELEM_PER_BATCH;
    double m0 = (double)s0 * invN - 0.5;   // f(0) - target
    double m1 = (double)s1 * invN;         // f'(0)
    double m2 = 0.5 * (double)s2 * invN;   // f''(0)/2

    double c = 0.0;
    #pragma unroll
    for (int it = 0; it < 3; it++) {
        double g  = m0 + c * (m1 + c * m2);
        double gp = m1 + 2.0 * m2 * c;
        c -= g / gp;
    }
    if (c >  20.0) c =  20.0;
    if (c < -20.0) c = -20.0;
    return (float)c;
}

// Stats over this block's stripe of `batch`; publish partial; ARRIVE on the
// batch's ticket counter (no wait). Returns thread0's ticket (garbage on
// other threads). Precise exp+rcp: these sums determine c (~5e-6 abs budget).
__device__ __forceinline__ unsigned
stats_pass(const float4* __restrict__ base, int batch, int sub,
           float (*sh)[3])
{
    const int warp = threadIdx.x >> 5;
    const int lane = threadIdx.x & 31;

    float a0 = 0.f, a1 = 0.f, a2 = 0.f;
    #pragma unroll 4
    for (int k = 0; k < ITERS; k++) {
        float4 v = base[k * THREADS + threadIdx.x];
        float xs[4] = {v.x, v.y, v.z, v.w};
        #pragma unroll
        for (int j = 0; j < 4; j++) {
            float e = __expf(-xs[j]);
            float s = rcp_fast(1.0f + e);
            float u = __fmaf_rn(-s, s, s);        // s(1-s)
            float t = __fmaf_rn(-2.0f, s, 1.0f);  // 1-2s
            a0 += s;
            a1 += u;
            a2 = __fmaf_rn(u, t, a2);
        }
    }
    #pragma unroll
    for (int off = 16; off; off >>= 1) {
        a0 += __shfl_xor_sync(0xFFFFFFFFu, a0, off);
        a1 += __shfl_xor_sync(0xFFFFFFFFu, a1, off);
        a2 += __shfl_xor_sync(0xFFFFFFFFu, a2, off);
    }
    if (lane == 0) { sh[warp][0] = a0; sh[warp][1] = a1; sh[warp][2] = a2; }
    __syncthreads();

    unsigned ticket = 0;
    if (threadIdx.x == 0) {
        float t0 = 0.f, t1 = 0.f, t2 = 0.f;
        #pragma unroll
        for (int w = 0; w < THREADS / 32; w++) {
            t0 += sh[w][0]; t1 += sh[w][1]; t2 += sh[w][2];
        }
        g_partial[batch][sub] = make_float4(t0, t1, t2, 0.f);
        __threadfence();                               // publish before arrive
        ticket = atomicAdd(&g_bar[batch], 1u);
    }
    __syncthreads();   // sh reusable by the next stats_pass
    return ticket;
}

// WAIT on the batch barrier (normally already satisfied: we arrived one full
// stats-pass earlier), solve c, then out = sigmoid(x+c) via tanh.
// Re-read is last-use (.cs), store evict-first (.cs).
__device__ __forceinline__ void
out_pass(const float4* __restrict__ base, float4* __restrict__ obase,
         int batch, int sub, unsigned ticket, float* sc,
         float* __restrict__ c_out)
{
    if (threadIdx.x == 0) {
        // Monotonic epoch: each launch adds exactly 64 per batch, so the
        // target derived from our own ticket is arrival-order independent
        // (graph-replay / ncu-replay safe).
        unsigned target = (ticket / BLOCKS_PER_BATCH + 1u) * BLOCKS_PER_BATCH;
        for (;;) {
            unsigned v;
            asm volatile("ld.acquire.gpu.global.u32 %0, [%1];"
                         : "=r"(v) : "l"(&g_bar[batch]) : "memory");
            if (v >= target) break;
            __nanosleep(40);
        }
    }
    __syncthreads();

    if (threadIdx.x < 32) {
        float c = solve_c(batch, threadIdx.x & 31);
        if (threadIdx.x == 0) {
            *sc = c;
            if (c_out && sub == 0) c_out[batch] = c;
        }
    }
    __syncthreads();
    const float halfc = 0.5f * (*sc);

    #pragma unroll 4
    for (int k = 0; k < ITERS; k++) {
        const int i = k * THREADS + threadIdx.x;
        float4 v = __ldcs(&base[i]);   // L2-hot; last use -> evict-first
        float4 r;
        r.x = __fmaf_rn(0.5f, tanh_fast(__fmaf_rn(0.5f, v.x, halfc)), 0.5f);
        r.y = __fmaf_rn(0.5f, tanh_fast(__fmaf_rn(0.5f, v.y, halfc)), 0.5f);
        r.z = __fmaf_rn(0.5f, tanh_fast(__fmaf_rn(0.5f, v.z, halfc)), 0.5f);
        r.w = __fmaf_rn(0.5f, tanh_fast(__fmaf_rn(0.5f, v.w, halfc)), 0.5f);
        __stcs(&obase[i], r);          // evict-first: keep L2 for live stripes
    }
    __syncthreads();                   // sc reusable by the next out_pass
}

// ---------------------------------------------------------------------------
// Persistent kernel, software-pipelined across the per-batch barrier:
//   stats(b0) stats(b1) out(b0) stats(b2) out(b1) stats(b3) out(b2) out(b3)
// Barrier waits are nearly free (arrival happened one stats-pass earlier),
// and read- and write-streams to DRAM overlap throughout.
// ---------------------------------------------------------------------------
__global__ void __launch_bounds__(THREADS, 4)
fused_kernel(const float4* __restrict__ X, float4* __restrict__ O,
             float* __restrict__ c_out)
{
    const int sub = blockIdx.x & (BLOCKS_PER_BATCH - 1);  // stripe in batch
    const int bb  = blockIdx.x >> 6;                      // batch in round

    __shared__ float sh[THREADS / 32][3];
    __shared__ float sc;

    const int b0 = bb, b1 = BATCH_PER_ROUND + bb,
              b2 = 2 * BATCH_PER_ROUND + bb, b3 = 3 * BATCH_PER_ROUND + bb;

    const size_t off0 = (size_t)b0 * V4_PER_BATCH + (size_t)sub * V4_PER_STRIPE;
    const size_t off1 = (size_t)b1 * V4_PER_BATCH + (size_t)sub * V4_PER_STRIPE;
    const size_t off2 = (size_t)b2 * V4_PER_BATCH + (size_t)sub * V4_PER_STRIPE;
    const size_t off3 = (size_t)b3 * V4_PER_BATCH + (size_t)sub * V4_PER_STRIPE;

    unsigned u0 = stats_pass(X + off0, b0, sub, sh);
    unsigned u1 = stats_pass(X + off1, b1, sub, sh);
    out_pass(X + off0, O + off0, b0, sub, u0, &sc, c_out);
    unsigned u2 = stats_pass(X + off2, b2, sub, sh);
    out_pass(X + off1, O + off1, b1, sub, u1, &sc, c_out);
    unsigned u3 = stats_pass(X + off3, b3, sub, sh);
    out_pass(X + off2, O + off2, b2, sub, u2, &sc, c_out);
    out_pass(X + off3, O + off3, b3, sub, u3, &sc, c_out);
}

// ---------------------------------------------------------------------------
extern "C" void kernel_launch(void* const* d_in, const int* in_sizes, int n_in,
                              void* d_out, int out_size)
{
    const float* X = (const float*)d_in[0];
    float* out = (float*)d_out;

    const long long map_elems = (long long)NBATCH * ELEM_PER_BATCH;
    float* c_out = ((long long)out_size > map_elems) ? (out + map_elems) : nullptr;

    fused_kernel<<<NBLK, THREADS>>>((const float4*)X, (float4*)out, c_out);
}

// round 6
// speedup vs baseline: 1.1222x; 1.1222x over previous
#include <cuda_runtime.h>

// Geometry (fixed: importanceMap [32, 1024, 1024] fp32)
#define NBATCH            32
#define ELEM_PER_BATCH    (1 << 20)
#define V4_PER_BATCH      (1 << 18)                  // float4 per batch
#define NBLK              1024
#define THREADS           128
#define TASKS             4                          // batch-rounds per block
#define BLOCKS_PER_BATCH  128
#define BATCH_PER_ROUND   (NBLK / BLOCKS_PER_BATCH)  // 8
#define V4_PER_STRIPE     (V4_PER_BATCH / BLOCKS_PER_BATCH) // 2048 (32 KB)
#define ITERS             (V4_PER_STRIPE / THREADS)  // 16

// Deterministic scratch (no allocations). Partials: {sum s, sum s', sum s''}.
__device__ float4       g_partial[NBATCH][BLOCKS_PER_BATCH];
__device__ unsigned int g_bar[NBATCH];   // monotonic ticket counter per batch

__device__ __forceinline__ float rcp_fast(float x) {
    float r; asm("rcp.approx.f32 %0, %1;" : "=f"(r) : "f"(x)); return r;
}
__device__ __forceinline__ float tanh_fast(float x) {
    float r; asm("tanh.approx.f32 %0, %1;" : "=f"(r) : "f"(x)); return r;
}

// Deterministic per-batch solve from 128 block partials (fixed order ->
// bitwise-identical c in every block of the batch). Runs on warp 0.
__device__ __forceinline__ float solve_c(int batch, int lane)
{
    float4 p0 = __ldcg(&g_partial[batch][lane]);
    float4 p1 = __ldcg(&g_partial[batch][lane + 32]);
    float4 p2 = __ldcg(&g_partial[batch][lane + 64]);
    float4 p3 = __ldcg(&g_partial[batch][lane + 96]);
    float s0 = (p0.x + p1.x) + (p2.x + p3.x);
    float s1 = (p0.y + p1.y) + (p2.y + p3.y);
    float s2 = (p0.z + p1.z) + (p2.z + p3.z);
    #pragma unroll
    for (int off = 16; off; off >>= 1) {
        s0 += __shfl_xor_sync(0xFFFFFFFFu, s0, off);
        s1 += __shfl_xor_sync(0xFFFFFFFFu, s1, off);
        s2 += __shfl_xor_sync(0xFFFFFFFFu, s2, off);
    }
    s0 = __shfl_sync(0xFFFFFFFFu, s0, 0);
    s1 = __shfl_sync(0xFFFFFFFFu, s1, 0);
    s2 = __shfl_sync(0xFFFFFFFFu, s2, 0);

    const double invN = 1.0 / (double)ELEM_PER_BATCH;
    double m0 = (double)s0 * invN - 0.5;   // f(0) - target
    double m1 = (double)s1 * invN;         // f'(0)
    double m2 = 0.5 * (double)s2 * invN;   // f''(0)/2

    double c = 0.0;
    #pragma unroll
    for (int it = 0; it < 3; it++) {
        double g  = m0 + c * (m1 + c * m2);
        double gp = m1 + 2.0 * m2 * c;
        c -= g / gp;
    }
    if (c >  20.0) c =  20.0;
    if (c < -20.0) c = -20.0;
    return (float)c;
}

// Per-batch barrier: only this batch's 128 blocks must converge.
// Monotonic epoch tickets: each launch adds exactly 128 per batch, so
// target = (ticket/128 + 1)*128 is identical for every arrival order
// (graph-replay / ncu-replay safe).
__device__ __forceinline__ void batch_barrier(int batch) {
    __syncthreads();
    if (threadIdx.x == 0) {
        __threadfence();                       // publish partial before arrive
        unsigned t = atomicAdd(&g_bar[batch], 1u);
        unsigned target = (t / BLOCKS_PER_BATCH + 1u) * BLOCKS_PER_BATCH;
        for (;;) {
            unsigned v;
            asm volatile("ld.acquire.gpu.global.u32 %0, [%1];"
                         : "=r"(v) : "l"(&g_bar[batch]) : "memory");
            if (v >= target) break;
            __nanosleep(40);
        }
    }
    __syncthreads();
}

// ---------------------------------------------------------------------------
// Persistent kernel, 4 batch-rounds per block. Per round:
//   stats over own 32 KB stripe (precise exp+rcp; c budget ~5e-6 abs)
//   -> per-batch barrier (128 fine stripes; groups drift/overlap freely)
//   -> solve c -> out = sigmoid(x+c) via 0.5*tanh(z/2)+0.5 (1 MUFU/elem);
//      stripe re-read hits L1/L2, output stored evict-first.
// 1024 blocks x 128 threads: single co-resident wave, ~62% occupancy for
// latency hiding on both streaming phases.
// ---------------------------------------------------------------------------
__global__ void __launch_bounds__(THREADS, 10)
fused_kernel(const float4* __restrict__ X, float4* __restrict__ O,
             float* __restrict__ c_out)
{
    const int sub  = blockIdx.x & (BLOCKS_PER_BATCH - 1);  // stripe in batch
    const int bb   = blockIdx.x >> 7;                      // batch in round
    const int warp = threadIdx.x >> 5;
    const int lane = threadIdx.x & 31;

    __shared__ float sh[THREADS / 32][3];
    __shared__ float sc;

    #pragma unroll 1
    for (int t = 0; t < TASKS; t++) {
        const int batch = t * BATCH_PER_ROUND + bb;
        const float4* __restrict__ base =
            X + (size_t)batch * V4_PER_BATCH + (size_t)sub * V4_PER_STRIPE;
        float4* __restrict__ obase =
            O + (size_t)batch * V4_PER_BATCH + (size_t)sub * V4_PER_STRIPE;

        // ---- stats over stripe (precise path: determines c) ----
        float a0 = 0.f, a1 = 0.f, a2 = 0.f;
        #pragma unroll 4
        for (int k = 0; k < ITERS; k++) {
            float4 v = base[k * THREADS + threadIdx.x];
            float xs[4] = {v.x, v.y, v.z, v.w};
            #pragma unroll
            for (int j = 0; j < 4; j++) {
                float e = __expf(-xs[j]);             // FMUL + MUFU.EX2
                float s = rcp_fast(1.0f + e);         // FADD + MUFU.RCP
                float u = __fmaf_rn(-s, s, s);        // s(1-s)
                float tt = __fmaf_rn(-2.0f, s, 1.0f); // 1-2s
                a0 += s;
                a1 += u;
                a2 = __fmaf_rn(u, tt, a2);
            }
        }
        #pragma unroll
        for (int off = 16; off; off >>= 1) {
            a0 += __shfl_xor_sync(0xFFFFFFFFu, a0, off);
            a1 += __shfl_xor_sync(0xFFFFFFFFu, a1, off);
            a2 += __shfl_xor_sync(0xFFFFFFFFu, a2, off);
        }
        if (lane == 0) { sh[warp][0] = a0; sh[warp][1] = a1; sh[warp][2] = a2; }
        __syncthreads();
        if (threadIdx.x == 0) {
            float t0 = 0.f, t1 = 0.f, t2 = 0.f;
            #pragma unroll
            for (int w = 0; w < THREADS / 32; w++) {
                t0 += sh[w][0]; t1 += sh[w][1]; t2 += sh[w][2];
            }
            g_partial[batch][sub] = make_float4(t0, t1, t2, 0.f);
        }

        // ---- only this batch's 128 blocks must converge ----
        batch_barrier(batch);

        // ---- solve c (redundant per block, bitwise identical) ----
        if (threadIdx.x < 32) {
            float c = solve_c(batch, lane);
            if (threadIdx.x == 0) {
                sc = c;
                if (c_out && sub == 0) c_out[batch] = c;
            }
        }
        __syncthreads();
        const float halfc = 0.5f * sc;

        // ---- out = sigmoid(x+c) = 0.5*tanh((x+c)/2) + 0.5 ----
        #pragma unroll 4
        for (int k = 0; k < ITERS; k++) {
            const int i = k * THREADS + threadIdx.x;
            float4 v = __ldcs(&base[i]);   // L1/L2-hot; last use -> evict-first
            float4 r;
            r.x = __fmaf_rn(0.5f, tanh_fast(__fmaf_rn(0.5f, v.x, halfc)), 0.5f);
            r.y = __fmaf_rn(0.5f, tanh_fast(__fmaf_rn(0.5f, v.y, halfc)), 0.5f);
            r.z = __fmaf_rn(0.5f, tanh_fast(__fmaf_rn(0.5f, v.z, halfc)), 0.5f);
            r.w = __fmaf_rn(0.5f, tanh_fast(__fmaf_rn(0.5f, v.w, halfc)), 0.5f);
            __stcs(&obase[i], r);          // evict-first: keep L2 for live data
        }
        __syncthreads();                   // protect sh/sc reuse next round
    }
}

// ---------------------------------------------------------------------------
extern "C" void kernel_launch(void* const* d_in, const int* in_sizes, int n_in,
                              void* d_out, int out_size)
{
    const float* X = (const float*)d_in[0];
    float* out = (float*)d_out;

    const long long map_elems = (long long)NBATCH * ELEM_PER_BATCH;
    float* c_out = ((long long)out_size > map_elems) ? (out + map_elems) : nullptr;

    fused_kernel<<<NBLK, THREADS>>>((const float4*)X, (float4*)out, c_out);
}